// round 3
// baseline (speedup 1.0000x reference)
#include <cuda_runtime.h>
#include <cstdint>

// LSTM: H=64, gates=256, T=50, BN=262144 sequences, input feature dim = 1.
// gates_t = x_t * w_in + h_{t-1} @ W_hh^T + (b_ih + b_hh)
// c_t = sig(f)*c + sig(i)*tanh(g);  h_t = sig(o)*tanh(c_t)
//
// Design: 64 sequences per block (32 packed float2 pairs), 256 threads.
//   - W_hh^T staged in smem as Wt[m][256] (64 KB), reused by all 64 seqs.
//   - h lives in smem as packed pairs hs[pair][m]; rewritten every step.
//   - Thread (warp w, lane l): pairs p = 4w..4w+3, gates g = l + 32k, k=0..7.
//     k={0,1}->i, {2,3}->f, {4,5}->g, {6,7}->o for j=l and j=l+32.
//   - Inner loop: 32 fma.rn.f32x2 per m (packed pair math = 2x fp32 rate),
//     8 coalesced LDS.32 for W + 4 broadcast LDS.64 for h per warp per m.
//   - c state stays in registers (16 floats/thread).

#define Hh 64
#define Gg 256
#define Tt 50
#define SEQ_PB 64
#define PAIRS 32
#define THREADS 256
#define PPT 4
#define KG 8

typedef unsigned long long u64;

__device__ __forceinline__ u64 pk2(float x, float y) {
    u64 d; asm("mov.b64 %0, {%1, %2};" : "=l"(d) : "f"(x), "f"(y)); return d;
}
__device__ __forceinline__ void upk2(u64 v, float& x, float& y) {
    asm("mov.b64 {%0, %1}, %2;" : "=f"(x), "=f"(y) : "l"(v));
}
__device__ __forceinline__ u64 dup2(float x) {
    u64 d; asm("mov.b64 %0, {%1, %1};" : "=l"(d) : "f"(x)); return d;
}
__device__ __forceinline__ u64 fma2(u64 a, u64 b, u64 c) {
    u64 d; asm("fma.rn.f32x2 %0, %1, %2, %3;" : "=l"(d) : "l"(a), "l"(b), "l"(c)); return d;
}

__device__ __forceinline__ float ex2f_(float x) {
    float r; asm("ex2.approx.f32 %0, %1;" : "=f"(r) : "f"(x)); return r;
}
__device__ __forceinline__ float rcpf_(float x) {
    float r; asm("rcp.approx.f32 %0, %1;" : "=f"(r) : "f"(x)); return r;
}
// Accurate sigmoid: 1/(1+e^-x). ex2.approx + rcp.approx are ~1ulp-class; gates
// are bounded (|x| ~ 1), so no range issues. Abs err ~1e-7.
__device__ __forceinline__ float sigf_(float x) {
    float t = ex2f_(x * -1.4426950408889634f);  // e^{-x}
    return rcpf_(1.0f + t);
}
// Accurate tanh: sign-split (1-e^{-2|x|})/(1+e^{-2|x|}); no cancellation blowup
// because for small |x|, 1-t ~ 2|x| with abs error ~1e-7. Abs err ~1e-6.
__device__ __forceinline__ float tanhf_(float x) {
    float ax = fabsf(x);
    float t = ex2f_(ax * -2.8853900817779268f);  // e^{-2|x|}
    float r = (1.0f - t) * rcpf_(1.0f + t);
    return copysignf(r, x);
}

// Dynamic smem layout (byte offsets):
//   Wt  [64][256] float   @ 0        (65536 B)   W_hh^T, Wt[m*256+g] = W_hh[g*64+m]
//   xs  [50][64]  float   @ 65536    (12800 B)   xs[t*64+s] = x[seq_base+s][t]
//   hs  [32][64]  u64     @ 78336    (16384 B)   packed (h_seq2p, h_seq2p+1)[m]
//   wb  [256]     u64     @ 94720    (2048 B)    dup2(W_ih[g])
//   bb  [256]     u64     @ 96768    (2048 B)    dup2(b_ih[g]+b_hh[g])
#define SMEM_BYTES 98816

extern "C" __global__ void __launch_bounds__(THREADS, 2)
lstm_f32x2_kernel(const float* __restrict__ x_g,
                  const float* __restrict__ W_ih,
                  const float* __restrict__ W_hh,
                  const float* __restrict__ b_ih,
                  const float* __restrict__ b_hh,
                  float* __restrict__ out)
{
    extern __shared__ char smem[];
    float* Wt = (float*)smem;
    float* xs = (float*)(smem + 65536);
    u64*   hs = (u64*)(smem + 78336);
    u64*   wb = (u64*)(smem + 94720);
    u64*   bb = (u64*)(smem + 96768);

    const int tid = threadIdx.x;
    const int l   = tid & 31;
    const int w   = tid >> 5;
    const int p0  = w * PPT;
    const int seq_base = blockIdx.x * SEQ_PB;

    // Stage W_hh^T (coalesced global read; smem store conflicts are one-time)
    for (int idx = tid; idx < Hh * Gg; idx += THREADS) {
        int g = idx >> 6, m = idx & 63;
        Wt[m * Gg + g] = W_hh[idx];
    }
    // Pre-duplicated per-gate input weight and fused bias
    for (int g = tid; g < Gg; g += THREADS) {
        wb[g] = dup2(W_ih[g]);
        bb[g] = dup2(b_ih[g] + b_hh[g]);
    }
    // Stage input time series for this block's 64 sequences
    for (int idx = tid; idx < SEQ_PB * Tt; idx += THREADS) {
        int r = idx / Tt, t = idx - r * Tt;
        xs[t * 64 + r] = x_g[(seq_base + r) * Tt + t];
    }
    // h_0 = 0
    for (int idx = tid; idx < PAIRS * 64; idx += THREADS) hs[idx] = 0ULL;

    // c state in registers: [pair][j-half (l or l+32)][seq-in-pair]
    float c[PPT][2][2];
    #pragma unroll
    for (int p = 0; p < PPT; p++)
        #pragma unroll
        for (int jh = 0; jh < 2; jh++) { c[p][jh][0] = 0.0f; c[p][jh][1] = 0.0f; }

    __syncthreads();

    for (int t = 0; t < Tt; t++) {
        // ---- gate accumulators: acc = x * w_in + bias ----
        u64 acc[PPT][KG];
        {
            u64 x2[PPT];
            #pragma unroll
            for (int p = 0; p < PPT; p++)
                x2[p] = *(const u64*)&xs[t * 64 + (p0 + p) * 2];
            #pragma unroll
            for (int k = 0; k < KG; k++) {
                u64 wv = wb[l + 32 * k];
                u64 bv = bb[l + 32 * k];
                #pragma unroll
                for (int p = 0; p < PPT; p++)
                    acc[p][k] = fma2(x2[p], wv, bv);
            }
        }

        // ---- recurrent GEMV: acc += h @ W_hh^T (packed pairs) ----
        #pragma unroll 8
        for (int m = 0; m < Hh; m++) {
            u64 h2[PPT];
            #pragma unroll
            for (int p = 0; p < PPT; p++) h2[p] = hs[(p0 + p) * 64 + m];
            #pragma unroll
            for (int k = 0; k < KG; k++) {
                u64 wd = dup2(Wt[m * Gg + l + 32 * k]);
                #pragma unroll
                for (int p = 0; p < PPT; p++)
                    acc[p][k] = fma2(h2[p], wd, acc[p][k]);
            }
        }
        __syncthreads();  // all reads of hs complete before overwrite

        // ---- elementwise gates -> c, h; write new h pairs ----
        #pragma unroll
        for (int p = 0; p < PPT; p++) {
            #pragma unroll
            for (int jh = 0; jh < 2; jh++) {
                float gi0, gi1, gf0, gf1, gg0, gg1, go0, go1;
                upk2(acc[p][0 + jh], gi0, gi1);
                upk2(acc[p][2 + jh], gf0, gf1);
                upk2(acc[p][4 + jh], gg0, gg1);
                upk2(acc[p][6 + jh], go0, go1);
                float c0 = sigf_(gf0) * c[p][jh][0] + sigf_(gi0) * tanhf_(gg0);
                float c1 = sigf_(gf1) * c[p][jh][1] + sigf_(gi1) * tanhf_(gg1);
                c[p][jh][0] = c0;
                c[p][jh][1] = c1;
                float h0 = sigf_(go0) * tanhf_(c0);
                float h1 = sigf_(go1) * tanhf_(c1);
                hs[(p0 + p) * 64 + l + 32 * jh] = pk2(h0, h1);
            }
        }
        __syncthreads();  // new h visible before next step's reads
    }

    // ---- write h_final, coalesced ----
    for (int idx = tid; idx < SEQ_PB * Hh; idx += THREADS) {
        int s = idx >> 6, j = idx & 63;
        float lo, hi;
        upk2(hs[(s >> 1) * 64 + j], lo, hi);
        out[(seq_base + s) * Hh + j] = (s & 1) ? hi : lo;
    }
}

extern "C" void kernel_launch(void* const* d_in, const int* in_sizes, int n_in,
                              void* d_out, int out_size) {
    const float* x    = (const float*)d_in[0];  // dynamic (64,4096,50)
    const float* W_ih = (const float*)d_in[1];  // (256,1)
    const float* W_hh = (const float*)d_in[2];  // (256,64)
    const float* b_ih = (const float*)d_in[3];  // (256,)
    const float* b_hh = (const float*)d_in[4];  // (256,)
    float* out = (float*)d_out;                 // (64,4096,64)

    cudaFuncSetAttribute(lstm_f32x2_kernel,
                         cudaFuncAttributeMaxDynamicSharedMemorySize, SMEM_BYTES);

    const int n_blocks = (64 * 4096) / SEQ_PB;  // 4096
    lstm_f32x2_kernel<<<n_blocks, THREADS, SMEM_BYTES>>>(x, W_ih, W_hh, b_ih, b_hh, out);
}

// round 7
// speedup vs baseline: 1.9748x; 1.9748x over previous
#include <cuda_runtime.h>
#include <cuda_fp16.h>
#include <cstdint>

// LSTM via legacy mma.sync (compiles for plain sm_100 — tcgen05 does NOT).
// H=64, gates=256, T=50, 262144 seqs, input dim 1.
// CTA = 256 seqs, 8 warps; warp owns 32 seqs (two m16 tiles) x 256 gates.
// Per step/warp: D[32x256] = h[32x64] @ W_hh^T via fp16 3-limb split:
//   h_hi*W_hi + h_hi*W_lo + h_lo*W_hi   (effectively fp32-exact)
// fp32 accum. Epilogue adds x*w_in + bias, runs sigmoid/tanh via ex2/rcp
// (1 MUFU each), writes h limbs back to the warp-private A tiles.
// No block syncs in the main loop (state is warp-private) — only __syncwarp.

typedef uint32_t u32;

#define THREADS 256
#define TSTEPS  50
#define SEQ_CTA 256

// smem byte offsets
#define OFF_WHI 0        // W_hh hi [256 g][64 k] f16, 128B rows, XOR-swz (32KB)
#define OFF_WLO 32768    // W_hh lo                                      (32KB)
#define OFF_HHI 65536    // h hi  [256 s][64 k] f16, 128B rows, swz      (32KB)
#define OFF_HLO 98304    // h lo                                         (32KB)
#define OFF_XS  131072   // x staged [50][256] f32                       (50KB)
#define OFF_WB  182272   // (w_in, bias) float2[256]                      (2KB)
#define SMEM_TOTAL 184320

__device__ __forceinline__ u32 smem_u32(const void* p) {
    u32 a;
    asm("{ .reg .u64 t; cvta.to.shared.u64 t, %1; cvt.u32.u64 %0, t; }"
        : "=r"(a) : "l"(p));
    return a;
}

#define LDSM4(r, a) asm volatile( \
    "ldmatrix.sync.aligned.m8n8.x4.shared.b16 {%0,%1,%2,%3}, [%4];" \
    : "=r"((r)[0]), "=r"((r)[1]), "=r"((r)[2]), "=r"((r)[3]) : "r"(a))

#define MMA(d, a, b0, b1) asm volatile( \
    "mma.sync.aligned.m16n8k16.row.col.f32.f16.f16.f32 " \
    "{%0,%1,%2,%3}, {%4,%5,%6,%7}, {%8,%9}, {%0,%1,%2,%3};" \
    : "+f"((d)[0]), "+f"((d)[1]), "+f"((d)[2]), "+f"((d)[3]) \
    : "r"((a)[0]), "r"((a)[1]), "r"((a)[2]), "r"((a)[3]), "r"(b0), "r"(b1))

__device__ __forceinline__ float ex2f_(float x){float r;asm("ex2.approx.f32 %0,%1;":"=f"(r):"f"(x));return r;}
__device__ __forceinline__ float rcpf_(float x){float r;asm("rcp.approx.f32 %0,%1;":"=f"(r):"f"(x));return r;}

extern "C" __global__ void __launch_bounds__(THREADS, 1)
lstm_hmma_kernel(const float* __restrict__ x_g,
                 const float* __restrict__ W_ih,
                 const float* __restrict__ W_hh,
                 const float* __restrict__ b_ih,
                 const float* __restrict__ b_hh,
                 float* __restrict__ out)
{
    extern __shared__ char sm[];
    const u32 S = smem_u32(sm);
    const int tid  = threadIdx.x;
    const int lane = tid & 31;
    const int w    = tid >> 5;
    const int seq0 = blockIdx.x * SEQ_CTA;

    // ---------------- one-time staging ----------------
    // W_hh fp16 limbs; byte(g, k) = g*128 + ((k*2) ^ ((g&7)<<4))
    for (int i = tid; i < 256 * 64; i += THREADS) {
        int g = i >> 6, k = i & 63;
        float wv = W_hh[i];
        __half hi = __float2half_rn(wv);
        __half lo = __float2half_rn(wv - __half2float(hi));
        u32 off = (u32)(g * 128) + (u32)((k * 2) ^ ((g & 7) << 4));
        *(__half*)(sm + OFF_WHI + off) = hi;
        *(__half*)(sm + OFF_WLO + off) = lo;
    }
    // h tiles zero (h0 = 0): both hi and lo (64KB contiguous)
    for (int i = tid; i < 65536 / 4; i += THREADS)
        ((u32*)(sm + OFF_HHI))[i] = 0u;
    // x staged: xs[t][s]
    float* xs = (float*)(sm + OFF_XS);
    for (int i = tid; i < SEQ_CTA * TSTEPS; i += THREADS) {
        int s = i / TSTEPS, t = i - s * TSTEPS;
        xs[t * SEQ_CTA + s] = x_g[(size_t)(seq0 + s) * TSTEPS + t];
    }
    // (w_in, bias)
    float2* wb = (float2*)(sm + OFF_WB);
    for (int g = tid; g < 256; g += THREADS) {
        float2 v; v.x = W_ih[g]; v.y = b_ih[g] + b_hh[g];
        wb[g] = v;
    }
    __syncthreads();

    // ---------------- per-thread constants ----------------
    const int r16   = lane & 15;          // A-frag row within m16
    const int khalf = lane >> 4;          // A-frag k-half (0/1)
    const int swzA  = (lane & 7) << 4;
    // A (h) tile addresses: warp rows 32w .. 32w+31
    const u32 a_hi_row = S + OFF_HHI + (u32)((w * 32 + r16) * 128);
    const u32 a_lo_row = S + OFF_HLO + (u32)((w * 32 + r16) * 128);
    u32 acol[4];
    #pragma unroll
    for (int kt = 0; kt < 4; kt++)
        acol[kt] = (u32)((kt * 32 + khalf * 16) ^ swzA);
    // B addresses: row = n0 + (lane&7); matrix sel = lane>>3 picks k-block of 8
    const int brow7 = lane & 7;
    const u32 swzB  = (u32)(brow7 << 4);
    const u32 bcol0 = (u32)(((lane >> 3) * 16)      ^ swzB);  // k 0..31
    const u32 bcol1 = (u32)((64 + (lane >> 3) * 16) ^ swzB);  // k 32..63
    const u32 brow_off = (u32)(brow7 * 128);
    // epilogue cell ownership
    const int qr = lane >> 2;             // row-in-8
    const int qc = (lane & 3) * 2;        // j offset within n8
    const u32 swzH = (u32)(qr << 4);

    const float L2E  = 1.4426950408889634f;
    const float L2E2 = 2.885390081777927f;

    float c[2][2][8][2];
    #pragma unroll
    for (int a = 0; a < 2; a++)
        #pragma unroll
        for (int b = 0; b < 2; b++)
            #pragma unroll
            for (int j = 0; j < 8; j++) { c[a][b][j][0] = 0.f; c[a][b][j][1] = 0.f; }

    // ---------------- time loop ----------------
    #pragma unroll 1
    for (int t = 0; t < TSTEPS; t++) {
        const bool last = (t == TSTEPS - 1);
        __syncwarp();   // previous step's h-stores visible to ldmatrix

        // A fragments (h hi + lo limbs), warp-private rows
        u32 AH[2][4][4], AL[2][4][4];
        #pragma unroll
        for (int mt = 0; mt < 2; mt++)
            #pragma unroll
            for (int kt = 0; kt < 4; kt++) {
                LDSM4(AH[mt][kt], a_hi_row + (u32)(mt * 2048) + acol[kt]);
                LDSM4(AL[mt][kt], a_lo_row + (u32)(mt * 2048) + acol[kt]);
            }

        // x for this thread's 4 cell rows
        float xv[2][2];
        #pragma unroll
        for (int mt = 0; mt < 2; mt++)
            #pragma unroll
            for (int rr = 0; rr < 2; rr++)
                xv[mt][rr] = xs[t * SEQ_CTA + w * 32 + mt * 16 + rr * 8 + qr];

        #pragma unroll
        for (int jt = 0; jt < 8; jt++) {
            float D[4][2][4];
            #pragma unroll
            for (int gb = 0; gb < 4; gb++)
                #pragma unroll
                for (int mt = 0; mt < 2; mt++) {
                    D[gb][mt][0] = 0.f; D[gb][mt][1] = 0.f;
                    D[gb][mt][2] = 0.f; D[gb][mt][3] = 0.f;
                }

            #pragma unroll
            for (int gb = 0; gb < 4; gb++) {
                const u32 nrow = (u32)((gb * 64 + jt * 8) * 128) + brow_off;
                u32 bh[8], bl[8];
                LDSM4(bh + 0, S + OFF_WHI + nrow + bcol0);
                LDSM4(bh + 4, S + OFF_WHI + nrow + bcol1);
                LDSM4(bl + 0, S + OFF_WLO + nrow + bcol0);
                LDSM4(bl + 4, S + OFF_WLO + nrow + bcol1);
                #pragma unroll
                for (int kt = 0; kt < 4; kt++) {
                    #pragma unroll
                    for (int mt = 0; mt < 2; mt++) {
                        MMA(D[gb][mt], AH[mt][kt], bh[2 * kt], bh[2 * kt + 1]);
                        MMA(D[gb][mt], AH[mt][kt], bl[2 * kt], bl[2 * kt + 1]);
                        MMA(D[gb][mt], AL[mt][kt], bh[2 * kt], bh[2 * kt + 1]);
                    }
                }
            }

            // per-jt gate weights/biases (broadcast LDS)
            float2 wbi[4][2];
            #pragma unroll
            for (int gb = 0; gb < 4; gb++) {
                wbi[gb][0] = wb[gb * 64 + jt * 8 + qc];
                wbi[gb][1] = wb[gb * 64 + jt * 8 + qc + 1];
            }

            // epilogue: 8 cells (2 mt x 2 rows x 2 cols)
            #pragma unroll
            for (int mt = 0; mt < 2; mt++) {
                #pragma unroll
                for (int rr = 0; rr < 2; rr++) {
                    const float x0 = xv[mt][rr];
                    float hvv[2];
                    #pragma unroll
                    for (int cc = 0; cc < 2; cc++) {
                        const int di = rr * 2 + cc;
                        float Gi = fmaf(x0, wbi[0][cc].x, D[0][mt][di] + wbi[0][cc].y);
                        float Gf = fmaf(x0, wbi[1][cc].x, D[1][mt][di] + wbi[1][cc].y);
                        float Gg = fmaf(x0, wbi[2][cc].x, D[2][mt][di] + wbi[2][cc].y);
                        float Go = fmaf(x0, wbi[3][cc].x, D[3][mt][di] + wbi[3][cc].y);
                        float ef = ex2f_(Gf * -L2E);
                        float sf = rcpf_(1.0f + ef);
                        float ei = ex2f_(Gi * -L2E);
                        float eg = ex2f_(Gg * -L2E2);
                        float itn = (1.0f - eg) * rcpf_((1.0f + ei) * (1.0f + eg));
                        float cn = fmaf(sf, c[mt][rr][jt][cc], itn);
                        c[mt][rr][jt][cc] = cn;
                        float eo = ex2f_(Go * -L2E);
                        float ec = ex2f_(fminf(cn * -L2E2, 80.0f));
                        hvv[cc] = (1.0f - ec) * rcpf_((1.0f + eo) * (1.0f + ec));
                    }
                    const int row = w * 32 + mt * 16 + rr * 8 + qr;
                    if (!last) {
                        u32 off = (u32)(row * 128)
                                + (u32)(((jt * 8 + qc) * 2) ^ swzH);
                        __half h0 = __float2half_rn(hvv[0]);
                        __half h1 = __float2half_rn(hvv[1]);
                        __half l0 = __float2half_rn(hvv[0] - __half2float(h0));
                        __half l1 = __float2half_rn(hvv[1] - __half2float(h1));
                        *(__half2*)(sm + OFF_HHI + off) = __halves2half2(h0, h1);
                        *(__half2*)(sm + OFF_HLO + off) = __halves2half2(l0, l1);
                    } else {
                        *(float2*)(out + (size_t)(seq0 + row) * 64 + jt * 8 + qc) =
                            make_float2(hvv[0], hvv[1]);
                    }
                }
            }
        }
    }
}

extern "C" void kernel_launch(void* const* d_in, const int* in_sizes, int n_in,
                              void* d_out, int out_size) {
    const float* x    = (const float*)d_in[0];  // dynamic (64,4096,50)
    const float* W_ih = (const float*)d_in[1];  // (256,1)
    const float* W_hh = (const float*)d_in[2];  // (256,64)
    const float* b_ih = (const float*)d_in[3];  // (256,)
    const float* b_hh = (const float*)d_in[4];  // (256,)
    float* out = (float*)d_out;                 // (64,4096,64)

    cudaFuncSetAttribute(lstm_hmma_kernel,
                         cudaFuncAttributeMaxDynamicSharedMemorySize, SMEM_TOTAL);

    const int n_blocks = (64 * 4096) / SEQ_CTA;  // 1024
    lstm_hmma_kernel<<<n_blocks, THREADS, SMEM_TOTAL>>>(x, W_ih, W_hh, b_ih, b_hh, out);
}

// round 10
// speedup vs baseline: 1.9980x; 1.0118x over previous
#include <cuda_runtime.h>
#include <cuda_fp16.h>
#include <cstdint>

// LSTM via legacy mma.sync (plain sm_100 target — tcgen05 unavailable).
// H=64, gates=256, T=50, 262144 seqs, input dim 1.
// CTA = 256 seqs, 16 warps; warp owns 16 seqs (one m16 tile) x 256 gates.
// Per step/warp: D[16x256] = h[16x64] @ W_hh^T via fp16 3-limb split:
//   h_hi*W_hi + h_hi*W_lo + h_lo*W_hi   (effectively fp32-exact)
// fp32 accum. Epilogue adds x*w_in + bias, sigmoid/tanh via ex2/rcp,
// writes h limbs back to warp-private A-tile rows. No block syncs in the
// main loop — only __syncwarp (state is warp-private).
// vs R7: per-warp tile halved (regs 255 -> ~128, no spills), warps/SMSP
// 2 -> 4, to lift tensor-pipe util from 45.6% toward its rt=8cyc roofline.

typedef uint32_t u32;

#define THREADS 512
#define TSTEPS  50
#define SEQ_CTA 256

// smem byte offsets
#define OFF_WHI 0        // W_hh hi [256 g][64 k] f16, 128B rows, XOR-swz (32KB)
#define OFF_WLO 32768    // W_hh lo                                      (32KB)
#define OFF_HHI 65536    // h hi  [256 s][64 k] f16, 128B rows, swz      (32KB)
#define OFF_HLO 98304    // h lo                                         (32KB)
#define OFF_XS  131072   // x staged [50][256] f32                       (50KB)
#define OFF_WB  182272   // (w_in, bias) float2[256]                      (2KB)
#define SMEM_TOTAL 184320

__device__ __forceinline__ u32 smem_u32(const void* p) {
    u32 a;
    asm("{ .reg .u64 t; cvta.to.shared.u64 t, %1; cvt.u32.u64 %0, t; }"
        : "=r"(a) : "l"(p));
    return a;
}

#define LDSM4(r, a) asm volatile( \
    "ldmatrix.sync.aligned.m8n8.x4.shared.b16 {%0,%1,%2,%3}, [%4];" \
    : "=r"((r)[0]), "=r"((r)[1]), "=r"((r)[2]), "=r"((r)[3]) : "r"(a))

#define MMA(d, a, b0, b1) asm volatile( \
    "mma.sync.aligned.m16n8k16.row.col.f32.f16.f16.f32 " \
    "{%0,%1,%2,%3}, {%4,%5,%6,%7}, {%8,%9}, {%0,%1,%2,%3};" \
    : "+f"((d)[0]), "+f"((d)[1]), "+f"((d)[2]), "+f"((d)[3]) \
    : "r"((a)[0]), "r"((a)[1]), "r"((a)[2]), "r"((a)[3]), "r"(b0), "r"(b1))

__device__ __forceinline__ float ex2f_(float x){float r;asm("ex2.approx.f32 %0,%1;":"=f"(r):"f"(x));return r;}
__device__ __forceinline__ float rcpf_(float x){float r;asm("rcp.approx.f32 %0,%1;":"=f"(r):"f"(x));return r;}

extern "C" __global__ void __launch_bounds__(THREADS, 1)
lstm_hmma_kernel(const float* __restrict__ x_g,
                 const float* __restrict__ W_ih,
                 const float* __restrict__ W_hh,
                 const float* __restrict__ b_ih,
                 const float* __restrict__ b_hh,
                 float* __restrict__ out)
{
    extern __shared__ char sm[];
    const u32 S = smem_u32(sm);
    const int tid  = threadIdx.x;
    const int lane = tid & 31;
    const int w    = tid >> 5;           // 0..15
    const int seq0 = blockIdx.x * SEQ_CTA;

    // ---------------- one-time staging ----------------
    // W_hh fp16 limbs; byte(g, k) = g*128 + ((k*2) ^ ((g&7)<<4))
    for (int i = tid; i < 256 * 64; i += THREADS) {
        int g = i >> 6, k = i & 63;
        float wv = W_hh[i];
        __half hi = __float2half_rn(wv);
        __half lo = __float2half_rn(wv - __half2float(hi));
        u32 off = (u32)(g * 128) + (u32)((k * 2) ^ ((g & 7) << 4));
        *(__half*)(sm + OFF_WHI + off) = hi;
        *(__half*)(sm + OFF_WLO + off) = lo;
    }
    // h tiles zero (h0 = 0): hi + lo, 64KB contiguous
    for (int i = tid; i < 65536 / 4; i += THREADS)
        ((u32*)(sm + OFF_HHI))[i] = 0u;
    // x staged: xs[t][s]
    float* xs = (float*)(sm + OFF_XS);
    for (int i = tid; i < SEQ_CTA * TSTEPS; i += THREADS) {
        int s = i / TSTEPS, t = i - s * TSTEPS;
        xs[t * SEQ_CTA + s] = x_g[(size_t)(seq0 + s) * TSTEPS + t];
    }
    // (w_in, bias)
    float2* wb = (float2*)(sm + OFF_WB);
    for (int g = tid; g < 256; g += THREADS) {
        float2 v; v.x = W_ih[g]; v.y = b_ih[g] + b_hh[g];
        wb[g] = v;
    }
    __syncthreads();

    // ---------------- per-thread constants ----------------
    const int r16   = lane & 15;          // A-frag row within m16
    const int khalf = lane >> 4;          // A-frag k-half (0/1)
    const int swzA  = (lane & 7) << 4;
    // A (h) tile addresses: warp rows 16w .. 16w+15
    const u32 a_hi_row = S + OFF_HHI + (u32)((w * 16 + r16) * 128);
    const u32 a_lo_row = S + OFF_HLO + (u32)((w * 16 + r16) * 128);
    u32 acol[4];
    #pragma unroll
    for (int kt = 0; kt < 4; kt++)
        acol[kt] = (u32)((kt * 32 + khalf * 16) ^ swzA);
    // B addresses: row = n0 + (lane&7); matrix sel = lane>>3 picks k-block of 8
    const int brow7 = lane & 7;
    const u32 swzB  = (u32)(brow7 << 4);
    const u32 bcol0 = (u32)(((lane >> 3) * 16)      ^ swzB);  // k 0..31
    const u32 bcol1 = (u32)((64 + (lane >> 3) * 16) ^ swzB);  // k 32..63
    const u32 brow_off = (u32)(brow7 * 128);
    // epilogue cell ownership
    const int qr = lane >> 2;             // row-in-8
    const int qc = (lane & 3) * 2;        // j offset within n8
    const u32 swzH = (u32)(qr << 4);

    const float L2E  = 1.4426950408889634f;
    const float L2E2 = 2.885390081777927f;

    float c[2][8][2];                     // [row-half][jt][col]
    #pragma unroll
    for (int b = 0; b < 2; b++)
        #pragma unroll
        for (int j = 0; j < 8; j++) { c[b][j][0] = 0.f; c[b][j][1] = 0.f; }

    // ---------------- time loop ----------------
    #pragma unroll 1
    for (int t = 0; t < TSTEPS; t++) {
        const bool last = (t == TSTEPS - 1);
        __syncwarp();   // previous step's h-stores visible to ldmatrix

        // A fragments (h hi + lo limbs), warp-private rows
        u32 AH[4][4], AL[4][4];
        #pragma unroll
        for (int kt = 0; kt < 4; kt++) {
            LDSM4(AH[kt], a_hi_row + acol[kt]);
            LDSM4(AL[kt], a_lo_row + acol[kt]);
        }

        // x for this thread's 2 cell rows
        float xv[2];
        #pragma unroll
        for (int rr = 0; rr < 2; rr++)
            xv[rr] = xs[t * SEQ_CTA + w * 16 + rr * 8 + qr];

        #pragma unroll
        for (int jt = 0; jt < 8; jt++) {
            float D[4][4];
            #pragma unroll
            for (int gb = 0; gb < 4; gb++) {
                D[gb][0] = 0.f; D[gb][1] = 0.f; D[gb][2] = 0.f; D[gb][3] = 0.f;
            }

            #pragma unroll
            for (int gb = 0; gb < 4; gb++) {
                const u32 nrow = (u32)((gb * 64 + jt * 8) * 128) + brow_off;
                u32 bh[8], bl[8];
                LDSM4(bh + 0, S + OFF_WHI + nrow + bcol0);
                LDSM4(bh + 4, S + OFF_WHI + nrow + bcol1);
                LDSM4(bl + 0, S + OFF_WLO + nrow + bcol0);
                LDSM4(bl + 4, S + OFF_WLO + nrow + bcol1);
                #pragma unroll
                for (int kt = 0; kt < 4; kt++) {
                    MMA(D[gb], AH[kt], bh[2 * kt], bh[2 * kt + 1]);
                    MMA(D[gb], AH[kt], bl[2 * kt], bl[2 * kt + 1]);
                    MMA(D[gb], AL[kt], bh[2 * kt], bh[2 * kt + 1]);
                }
            }

            // per-jt gate weights/biases (broadcast LDS)
            float2 wbi[4][2];
            #pragma unroll
            for (int gb = 0; gb < 4; gb++) {
                wbi[gb][0] = wb[gb * 64 + jt * 8 + qc];
                wbi[gb][1] = wb[gb * 64 + jt * 8 + qc + 1];
            }

            // epilogue: 4 cells (2 rows x 2 cols)
            #pragma unroll
            for (int rr = 0; rr < 2; rr++) {
                const float x0 = xv[rr];
                float hvv[2];
                #pragma unroll
                for (int cc = 0; cc < 2; cc++) {
                    const int di = rr * 2 + cc;
                    float Gi = fmaf(x0, wbi[0][cc].x, D[0][di] + wbi[0][cc].y);
                    float Gf = fmaf(x0, wbi[1][cc].x, D[1][di] + wbi[1][cc].y);
                    float Gg = fmaf(x0, wbi[2][cc].x, D[2][di] + wbi[2][cc].y);
                    float Go = fmaf(x0, wbi[3][cc].x, D[3][di] + wbi[3][cc].y);
                    float ef = ex2f_(Gf * -L2E);
                    float sf = rcpf_(1.0f + ef);
                    float ei = ex2f_(Gi * -L2E);
                    float eg = ex2f_(Gg * -L2E2);
                    float itn = (1.0f - eg) * rcpf_((1.0f + ei) * (1.0f + eg));
                    float cn = fmaf(sf, c[rr][jt][cc], itn);
                    c[rr][jt][cc] = cn;
                    float eo = ex2f_(Go * -L2E);
                    float ec = ex2f_(fminf(cn * -L2E2, 80.0f));
                    hvv[cc] = (1.0f - ec) * rcpf_((1.0f + eo) * (1.0f + ec));
                }
                const int row = w * 16 + rr * 8 + qr;
                if (!last) {
                    u32 off = (u32)(row * 128)
                            + (u32)(((jt * 8 + qc) * 2) ^ swzH);
                    __half h0 = __float2half_rn(hvv[0]);
                    __half h1 = __float2half_rn(hvv[1]);
                    __half l0 = __float2half_rn(hvv[0] - __half2float(h0));
                    __half l1 = __float2half_rn(hvv[1] - __half2float(h1));
                    *(__half2*)(sm + OFF_HHI + off) = __halves2half2(h0, h1);
                    *(__half2*)(sm + OFF_HLO + off) = __halves2half2(l0, l1);
                } else {
                    *(float2*)(out + (size_t)(seq0 + row) * 64 + jt * 8 + qc) =
                        make_float2(hvv[0], hvv[1]);
                }
            }
        }
    }
}

extern "C" void kernel_launch(void* const* d_in, const int* in_sizes, int n_in,
                              void* d_out, int out_size) {
    const float* x    = (const float*)d_in[0];  // dynamic (64,4096,50)
    const float* W_ih = (const float*)d_in[1];  // (256,1)
    const float* W_hh = (const float*)d_in[2];  // (256,64)
    const float* b_ih = (const float*)d_in[3];  // (256,)
    const float* b_hh = (const float*)d_in[4];  // (256,)
    float* out = (float*)d_out;                 // (64,4096,64)

    cudaFuncSetAttribute(lstm_hmma_kernel,
                         cudaFuncAttributeMaxDynamicSharedMemorySize, SMEM_TOTAL);

    const int n_blocks = (64 * 4096) / SEQ_CTA;  // 1024
    lstm_hmma_kernel<<<n_blocks, THREADS, SMEM_TOTAL>>>(x, W_ih, W_hh, b_ih, b_hh, out);
}

// round 11
// speedup vs baseline: 2.3438x; 1.1731x over previous
#include <cuda_runtime.h>
#include <cuda_fp16.h>
#include <cstdint>

// LSTM via legacy mma.sync (plain sm_100 target — tcgen05 unavailable).
// H=64, gates=256, T=50, 262144 seqs, input dim 1.
// CTA = 256 seqs, 16 warps; warp owns 16 seqs (one m16 tile) x 256 gates.
// Per step/warp: D[16x256] = h[16x64] @ W_hh^T with W in TWO exact fp16
// limbs and h in ONE fp16 limb (h quant err ~2^-12; final rel_err ~1e-4).
// Each gate-block's MMAs use TWO accumulators (W_hi chain / W_lo chain,
// merged in the epilogue) so RAW chain depth is 4, not 12 (R10 finding:
// perf was bound by the serial MMA accumulator chain, not any pipe).
// fp32 accum. Epilogue adds x*w_in + bias, sigmoid/tanh via ex2/rcp,
// writes h (fp16) back to warp-private A-tile rows. No block syncs in the
// main loop — only __syncwarp (state is warp-private).

typedef uint32_t u32;

#define THREADS 512
#define TSTEPS  50
#define SEQ_CTA 256

// smem byte offsets
#define OFF_WHI 0        // W_hh hi [256 g][64 k] f16, 128B rows, XOR-swz (32KB)
#define OFF_WLO 32768    // W_hh lo                                      (32KB)
#define OFF_HHI 65536    // h  [256 s][64 k] f16, 128B rows, swz         (32KB)
#define OFF_XS  98304    // x staged [50][256] f32                       (50KB)
#define OFF_WB  149504   // (w_in, bias) float2[256]                      (2KB)
#define SMEM_TOTAL 151552

__device__ __forceinline__ u32 smem_u32(const void* p) {
    u32 a;
    asm("{ .reg .u64 t; cvta.to.shared.u64 t, %1; cvt.u32.u64 %0, t; }"
        : "=r"(a) : "l"(p));
    return a;
}

#define LDSM4(r, a) asm volatile( \
    "ldmatrix.sync.aligned.m8n8.x4.shared.b16 {%0,%1,%2,%3}, [%4];" \
    : "=r"((r)[0]), "=r"((r)[1]), "=r"((r)[2]), "=r"((r)[3]) : "r"(a))

#define MMA(d, a, b0, b1) asm volatile( \
    "mma.sync.aligned.m16n8k16.row.col.f32.f16.f16.f32 " \
    "{%0,%1,%2,%3}, {%4,%5,%6,%7}, {%8,%9}, {%0,%1,%2,%3};" \
    : "+f"((d)[0]), "+f"((d)[1]), "+f"((d)[2]), "+f"((d)[3]) \
    : "r"((a)[0]), "r"((a)[1]), "r"((a)[2]), "r"((a)[3]), "r"(b0), "r"(b1))

__device__ __forceinline__ float ex2f_(float x){float r;asm("ex2.approx.f32 %0,%1;":"=f"(r):"f"(x));return r;}
__device__ __forceinline__ float rcpf_(float x){float r;asm("rcp.approx.f32 %0,%1;":"=f"(r):"f"(x));return r;}

extern "C" __global__ void __launch_bounds__(THREADS, 1)
lstm_hmma_kernel(const float* __restrict__ x_g,
                 const float* __restrict__ W_ih,
                 const float* __restrict__ W_hh,
                 const float* __restrict__ b_ih,
                 const float* __restrict__ b_hh,
                 float* __restrict__ out)
{
    extern __shared__ char sm[];
    const u32 S = smem_u32(sm);
    const int tid  = threadIdx.x;
    const int lane = tid & 31;
    const int w    = tid >> 5;           // 0..15
    const int seq0 = blockIdx.x * SEQ_CTA;

    // ---------------- one-time staging ----------------
    // W_hh fp16 limbs; byte(g, k) = g*128 + ((k*2) ^ ((g&7)<<4))
    for (int i = tid; i < 256 * 64; i += THREADS) {
        int g = i >> 6, k = i & 63;
        float wv = W_hh[i];
        __half hi = __float2half_rn(wv);
        __half lo = __float2half_rn(wv - __half2float(hi));
        u32 off = (u32)(g * 128) + (u32)((k * 2) ^ ((g & 7) << 4));
        *(__half*)(sm + OFF_WHI + off) = hi;
        *(__half*)(sm + OFF_WLO + off) = lo;
    }
    // h tile zero (h0 = 0)
    for (int i = tid; i < 32768 / 4; i += THREADS)
        ((u32*)(sm + OFF_HHI))[i] = 0u;
    // x staged: xs[t][s]
    float* xs = (float*)(sm + OFF_XS);
    for (int i = tid; i < SEQ_CTA * TSTEPS; i += THREADS) {
        int s = i / TSTEPS, t = i - s * TSTEPS;
        xs[t * SEQ_CTA + s] = x_g[(size_t)(seq0 + s) * TSTEPS + t];
    }
    // (w_in, bias)
    float2* wb = (float2*)(sm + OFF_WB);
    for (int g = tid; g < 256; g += THREADS) {
        float2 v; v.x = W_ih[g]; v.y = b_ih[g] + b_hh[g];
        wb[g] = v;
    }
    __syncthreads();

    // ---------------- per-thread constants ----------------
    const int r16   = lane & 15;          // A-frag row within m16
    const int khalf = lane >> 4;          // A-frag k-half (0/1)
    const int swzA  = (lane & 7) << 4;
    // A (h) tile addresses: warp rows 16w .. 16w+15
    const u32 a_row = S + OFF_HHI + (u32)((w * 16 + r16) * 128);
    u32 acol[4];
    #pragma unroll
    for (int kt = 0; kt < 4; kt++)
        acol[kt] = (u32)((kt * 32 + khalf * 16) ^ swzA);
    // B addresses: row = n0 + (lane&7); matrix sel = lane>>3 picks k-block of 8
    const int brow7 = lane & 7;
    const u32 swzB  = (u32)(brow7 << 4);
    const u32 bcol0 = (u32)(((lane >> 3) * 16)      ^ swzB);  // k 0..31
    const u32 bcol1 = (u32)((64 + (lane >> 3) * 16) ^ swzB);  // k 32..63
    const u32 brow_off = (u32)(brow7 * 128);
    // epilogue cell ownership
    const int qr = lane >> 2;             // row-in-8
    const int qc = (lane & 3) * 2;        // j offset within n8
    const u32 swzH = (u32)(qr << 4);

    const float L2E  = 1.4426950408889634f;
    const float L2E2 = 2.885390081777927f;

    float c[2][8][2];                     // [row-half][jt][col]
    #pragma unroll
    for (int b = 0; b < 2; b++)
        #pragma unroll
        for (int j = 0; j < 8; j++) { c[b][j][0] = 0.f; c[b][j][1] = 0.f; }

    // ---------------- time loop ----------------
    #pragma unroll 1
    for (int t = 0; t < TSTEPS; t++) {
        const bool last = (t == TSTEPS - 1);
        __syncwarp();   // previous step's h-stores visible to ldmatrix

        // A fragments (h), warp-private rows
        u32 AH[4][4];
        #pragma unroll
        for (int kt = 0; kt < 4; kt++)
            LDSM4(AH[kt], a_row + acol[kt]);

        // x for this thread's 2 cell rows
        float xv[2];
        #pragma unroll
        for (int rr = 0; rr < 2; rr++)
            xv[rr] = xs[t * SEQ_CTA + w * 16 + rr * 8 + qr];

        #pragma unroll
        for (int jt = 0; jt < 8; jt++) {
            // Two accumulators per gate-block: W_hi chain and W_lo chain,
            // each only 4 MMAs deep (RAW). Merged in the epilogue.
            float D0[4][4], D1[4][4];
            #pragma unroll
            for (int gb = 0; gb < 4; gb++)
                #pragma unroll
                for (int i = 0; i < 4; i++) { D0[gb][i] = 0.f; D1[gb][i] = 0.f; }

            #pragma unroll
            for (int gb = 0; gb < 4; gb++) {
                const u32 nrow = (u32)((gb * 64 + jt * 8) * 128) + brow_off;
                u32 bh[8], bl[8];
                LDSM4(bh + 0, S + OFF_WHI + nrow + bcol0);
                LDSM4(bh + 4, S + OFF_WHI + nrow + bcol1);
                LDSM4(bl + 0, S + OFF_WLO + nrow + bcol0);
                LDSM4(bl + 4, S + OFF_WLO + nrow + bcol1);
                #pragma unroll
                for (int kt = 0; kt < 4; kt++) {
                    MMA(D0[gb], AH[kt], bh[2 * kt], bh[2 * kt + 1]);
                    MMA(D1[gb], AH[kt], bl[2 * kt], bl[2 * kt + 1]);
                }
            }

            // per-jt gate weights/biases (broadcast LDS)
            float2 wbi[4][2];
            #pragma unroll
            for (int gb = 0; gb < 4; gb++) {
                wbi[gb][0] = wb[gb * 64 + jt * 8 + qc];
                wbi[gb][1] = wb[gb * 64 + jt * 8 + qc + 1];
            }

            // epilogue: 4 cells (2 rows x 2 cols)
            #pragma unroll
            for (int rr = 0; rr < 2; rr++) {
                const float x0 = xv[rr];
                float hvv[2];
                #pragma unroll
                for (int cc = 0; cc < 2; cc++) {
                    const int di = rr * 2 + cc;
                    float Gi = fmaf(x0, wbi[0][cc].x,
                                    (D0[0][di] + D1[0][di]) + wbi[0][cc].y);
                    float Gf = fmaf(x0, wbi[1][cc].x,
                                    (D0[1][di] + D1[1][di]) + wbi[1][cc].y);
                    float Gg = fmaf(x0, wbi[2][cc].x,
                                    (D0[2][di] + D1[2][di]) + wbi[2][cc].y);
                    float Go = fmaf(x0, wbi[3][cc].x,
                                    (D0[3][di] + D1[3][di]) + wbi[3][cc].y);
                    float ef = ex2f_(Gf * -L2E);
                    float sf = rcpf_(1.0f + ef);
                    float ei = ex2f_(Gi * -L2E);
                    float eg = ex2f_(Gg * -L2E2);
                    float itn = (1.0f - eg) * rcpf_((1.0f + ei) * (1.0f + eg));
                    float cn = fmaf(sf, c[rr][jt][cc], itn);
                    c[rr][jt][cc] = cn;
                    float eo = ex2f_(Go * -L2E);
                    float ec = ex2f_(fminf(cn * -L2E2, 80.0f));
                    hvv[cc] = (1.0f - ec) * rcpf_((1.0f + eo) * (1.0f + ec));
                }
                const int row = w * 16 + rr * 8 + qr;
                if (!last) {
                    u32 off = (u32)(row * 128)
                            + (u32)(((jt * 8 + qc) * 2) ^ swzH);
                    *(__half2*)(sm + OFF_HHI + off) =
                        __halves2half2(__float2half_rn(hvv[0]),
                                       __float2half_rn(hvv[1]));
                } else {
                    *(float2*)(out + (size_t)(seq0 + row) * 64 + jt * 8 + qc) =
                        make_float2(hvv[0], hvv[1]);
                }
            }
        }
    }
}

extern "C" void kernel_launch(void* const* d_in, const int* in_sizes, int n_in,
                              void* d_out, int out_size) {
    const float* x    = (const float*)d_in[0];  // dynamic (64,4096,50)
    const float* W_ih = (const float*)d_in[1];  // (256,1)
    const float* W_hh = (const float*)d_in[2];  // (256,64)
    const float* b_ih = (const float*)d_in[3];  // (256,)
    const float* b_hh = (const float*)d_in[4];  // (256,)
    float* out = (float*)d_out;                 // (64,4096,64)

    cudaFuncSetAttribute(lstm_hmma_kernel,
                         cudaFuncAttributeMaxDynamicSharedMemorySize, SMEM_TOTAL);

    const int n_blocks = (64 * 4096) / SEQ_CTA;  // 1024
    lstm_hmma_kernel<<<n_blocks, THREADS, SMEM_TOTAL>>>(x, W_ih, W_hh, b_ih, b_hh, out);
}

// round 12
// speedup vs baseline: 2.3752x; 1.0134x over previous
#include <cuda_runtime.h>
#include <cuda_fp16.h>
#include <cstdint>

// LSTM via legacy mma.sync (plain sm_100 target — tcgen05 unavailable).
// H=64, gates=256, T=50, 262144 seqs, input dim 1.
// CTA = 256 seqs, 16 warps; warp owns 16 seqs (one m16 tile) x 256 gates.
// Per step/warp: D[16x256] = h[16x64] @ W_hh^T, BOTH operands single fp16
// (W abs quant err <= 3e-5 since |W|<=0.125; h quant ~2^-12; measured-
// calibrated final rel_err ~1.5e-4, threshold 1e-3).
// Two accumulators per gate-block split by k (chain depth 2).
// Warps run the jt loop with a per-warp phase offset (0 or 4, compile-time
// via template) so SMSP warps de-convoy: half in MMA phase while half in
// epilogue phase (R11 finding: tensor busy == MMA floor but 64% idle from
// phase-locked warps).
// No block syncs in the main loop — only __syncwarp (state warp-private).

typedef uint32_t u32;

#define THREADS 512
#define TSTEPS  50
#define SEQ_CTA 256

// smem byte offsets
#define OFF_WHI 0        // W_hh fp16 [256 g][64 k], 128B rows, XOR-swz  (32KB)
#define OFF_HHI 32768    // h [256 s][64 k] f16, 128B rows, swz          (32KB)
#define OFF_XS  65536    // x staged [50][256] f32                       (50KB)
#define OFF_WB  116736   // (w_in, bias) float2[256]                      (2KB)
#define SMEM_TOTAL 118784

__device__ __forceinline__ u32 smem_u32(const void* p) {
    u32 a;
    asm("{ .reg .u64 t; cvta.to.shared.u64 t, %1; cvt.u32.u64 %0, t; }"
        : "=r"(a) : "l"(p));
    return a;
}

#define LDSM4(r, a) asm volatile( \
    "ldmatrix.sync.aligned.m8n8.x4.shared.b16 {%0,%1,%2,%3}, [%4];" \
    : "=r"((r)[0]), "=r"((r)[1]), "=r"((r)[2]), "=r"((r)[3]) : "r"(a))

#define MMA(d, a, b0, b1) asm volatile( \
    "mma.sync.aligned.m16n8k16.row.col.f32.f16.f16.f32 " \
    "{%0,%1,%2,%3}, {%4,%5,%6,%7}, {%8,%9}, {%0,%1,%2,%3};" \
    : "+f"((d)[0]), "+f"((d)[1]), "+f"((d)[2]), "+f"((d)[3]) \
    : "r"((a)[0]), "r"((a)[1]), "r"((a)[2]), "r"((a)[3]), "r"(b0), "r"(b1))

__device__ __forceinline__ float ex2f_(float x){float r;asm("ex2.approx.f32 %0,%1;":"=f"(r):"f"(x));return r;}
__device__ __forceinline__ float rcpf_(float x){float r;asm("rcp.approx.f32 %0,%1;":"=f"(r):"f"(x));return r;}

template<int PH>
__device__ __forceinline__ void run_time_loop(
    char* sm, u32 S, const float* xs, const float2* wb, float* out,
    int w, int seq0,
    u32 a_row, u32 acol0, u32 acol1, u32 acol2, u32 acol3,
    u32 bcol0, u32 bcol1, u32 brow_off,
    int qr, int qc, u32 swzH)
{
    const float L2E  = 1.4426950408889634f;
    const float L2E2 = 2.885390081777927f;

    float c[2][8][2];
    #pragma unroll
    for (int b = 0; b < 2; b++)
        #pragma unroll
        for (int j = 0; j < 8; j++) { c[b][j][0] = 0.f; c[b][j][1] = 0.f; }

    const u32 acol[4] = {acol0, acol1, acol2, acol3};

    #pragma unroll 1
    for (int t = 0; t < TSTEPS; t++) {
        const bool last = (t == TSTEPS - 1);
        __syncwarp();   // previous step's h-stores visible to ldmatrix

        // A fragments (h), warp-private rows
        u32 AH[4][4];
        #pragma unroll
        for (int kt = 0; kt < 4; kt++)
            LDSM4(AH[kt], a_row + acol[kt]);

        // x for this thread's 2 cell rows
        float xv[2];
        #pragma unroll
        for (int rr = 0; rr < 2; rr++)
            xv[rr] = xs[t * SEQ_CTA + w * 16 + rr * 8 + qr];

        #pragma unroll
        for (int q = 0; q < 8; q++) {
            const int jt = (q + PH) & 7;   // compile-time per iteration
            // Two accumulators per gate-block, split by k: chain depth 2.
            float D0[4][4], D1[4][4];
            #pragma unroll
            for (int gb = 0; gb < 4; gb++)
                #pragma unroll
                for (int i = 0; i < 4; i++) { D0[gb][i] = 0.f; D1[gb][i] = 0.f; }

            #pragma unroll
            for (int gb = 0; gb < 4; gb++) {
                const u32 bb = S + OFF_WHI
                             + (u32)((gb * 64 + jt * 8) * 128) + brow_off;
                u32 bh[8];
                LDSM4(bh + 0, bb + bcol0);
                LDSM4(bh + 4, bb + bcol1);
                MMA(D0[gb], AH[0], bh[0], bh[1]);
                MMA(D0[gb], AH[1], bh[2], bh[3]);
                MMA(D1[gb], AH[2], bh[4], bh[5]);
                MMA(D1[gb], AH[3], bh[6], bh[7]);
            }

            // per-jt gate weights/biases (broadcast LDS)
            float2 wbi[4][2];
            #pragma unroll
            for (int gb = 0; gb < 4; gb++) {
                wbi[gb][0] = wb[gb * 64 + jt * 8 + qc];
                wbi[gb][1] = wb[gb * 64 + jt * 8 + qc + 1];
            }

            // epilogue: 4 cells (2 rows x 2 cols)
            #pragma unroll
            for (int rr = 0; rr < 2; rr++) {
                const float x0 = xv[rr];
                float hvv[2];
                #pragma unroll
                for (int cc = 0; cc < 2; cc++) {
                    const int di = rr * 2 + cc;
                    float Gi = fmaf(x0, wbi[0][cc].x,
                                    (D0[0][di] + D1[0][di]) + wbi[0][cc].y);
                    float Gf = fmaf(x0, wbi[1][cc].x,
                                    (D0[1][di] + D1[1][di]) + wbi[1][cc].y);
                    float Gg = fmaf(x0, wbi[2][cc].x,
                                    (D0[2][di] + D1[2][di]) + wbi[2][cc].y);
                    float Go = fmaf(x0, wbi[3][cc].x,
                                    (D0[3][di] + D1[3][di]) + wbi[3][cc].y);
                    float ef = ex2f_(Gf * -L2E);
                    float sf = rcpf_(1.0f + ef);
                    float ei = ex2f_(Gi * -L2E);
                    float eg = ex2f_(Gg * -L2E2);
                    float itn = (1.0f - eg) * rcpf_((1.0f + ei) * (1.0f + eg));
                    float cn = fmaf(sf, c[rr][jt][cc], itn);
                    c[rr][jt][cc] = cn;
                    float eo = ex2f_(Go * -L2E);
                    float ec = ex2f_(fminf(cn * -L2E2, 80.0f));
                    hvv[cc] = (1.0f - ec) * rcpf_((1.0f + eo) * (1.0f + ec));
                }
                const int row = w * 16 + rr * 8 + qr;
                if (!last) {
                    u32 off = (u32)(row * 128)
                            + (u32)(((jt * 8 + qc) * 2) ^ swzH);
                    *(__half2*)(sm + OFF_HHI + off) =
                        __halves2half2(__float2half_rn(hvv[0]),
                                       __float2half_rn(hvv[1]));
                } else {
                    *(float2*)(out + (size_t)(seq0 + row) * 64 + jt * 8 + qc) =
                        make_float2(hvv[0], hvv[1]);
                }
            }
        }
    }
}

extern "C" __global__ void __launch_bounds__(THREADS, 1)
lstm_hmma_kernel(const float* __restrict__ x_g,
                 const float* __restrict__ W_ih,
                 const float* __restrict__ W_hh,
                 const float* __restrict__ b_ih,
                 const float* __restrict__ b_hh,
                 float* __restrict__ out)
{
    extern __shared__ char sm[];
    const u32 S = smem_u32(sm);
    const int tid  = threadIdx.x;
    const int lane = tid & 31;
    const int w    = tid >> 5;           // 0..15
    const int seq0 = blockIdx.x * SEQ_CTA;

    // ---------------- one-time staging ----------------
    // W_hh fp16; byte(g, k) = g*128 + ((k*2) ^ ((g&7)<<4))
    for (int i = tid; i < 256 * 64; i += THREADS) {
        int g = i >> 6, k = i & 63;
        u32 off = (u32)(g * 128) + (u32)((k * 2) ^ ((g & 7) << 4));
        *(__half*)(sm + OFF_WHI + off) = __float2half_rn(W_hh[i]);
    }
    // h tile zero (h0 = 0)
    for (int i = tid; i < 32768 / 4; i += THREADS)
        ((u32*)(sm + OFF_HHI))[i] = 0u;
    // x staged: xs[t][s]
    float* xs = (float*)(sm + OFF_XS);
    for (int i = tid; i < SEQ_CTA * TSTEPS; i += THREADS) {
        int s = i / TSTEPS, t = i - s * TSTEPS;
        xs[t * SEQ_CTA + s] = x_g[(size_t)(seq0 + s) * TSTEPS + t];
    }
    // (w_in, bias)
    float2* wb = (float2*)(sm + OFF_WB);
    for (int g = tid; g < 256; g += THREADS) {
        float2 v; v.x = W_ih[g]; v.y = b_ih[g] + b_hh[g];
        wb[g] = v;
    }
    __syncthreads();

    // ---------------- per-thread constants ----------------
    const int r16   = lane & 15;          // A-frag row within m16
    const int khalf = lane >> 4;          // A-frag k-half (0/1)
    const int swzA  = (lane & 7) << 4;
    const u32 a_row = S + OFF_HHI + (u32)((w * 16 + r16) * 128);
    u32 acol[4];
    #pragma unroll
    for (int kt = 0; kt < 4; kt++)
        acol[kt] = (u32)((kt * 32 + khalf * 16) ^ swzA);
    const int brow7 = lane & 7;
    const u32 swzB  = (u32)(brow7 << 4);
    const u32 bcol0 = (u32)(((lane >> 3) * 16)      ^ swzB);  // k 0..31
    const u32 bcol1 = (u32)((64 + (lane >> 3) * 16) ^ swzB);  // k 32..63
    const u32 brow_off = (u32)(brow7 * 128);
    const int qr = lane >> 2;             // row-in-8
    const int qc = (lane & 3) * 2;        // j offset within n8
    const u32 swzH = (u32)(qr << 4);

    // Phase stagger: warps (w>>2) even run jt order 0..7, odd run 4..7,0..3.
    // Each SMSP (w%4) hosts warps with (w>>2) = 0,1,2,3 -> 2 of each phase.
    if (((w >> 2) & 1) == 0)
        run_time_loop<0>(sm, S, xs, wb, out, w, seq0, a_row,
                         acol[0], acol[1], acol[2], acol[3],
                         bcol0, bcol1, brow_off, qr, qc, swzH);
    else
        run_time_loop<4>(sm, S, xs, wb, out, w, seq0, a_row,
                         acol[0], acol[1], acol[2], acol[3],
                         bcol0, bcol1, brow_off, qr, qc, swzH);
}

extern "C" void kernel_launch(void* const* d_in, const int* in_sizes, int n_in,
                              void* d_out, int out_size) {
    const float* x    = (const float*)d_in[0];  // dynamic (64,4096,50)
    const float* W_ih = (const float*)d_in[1];  // (256,1)
    const float* W_hh = (const float*)d_in[2];  // (256,64)
    const float* b_ih = (const float*)d_in[3];  // (256,)
    const float* b_hh = (const float*)d_in[4];  // (256,)
    float* out = (float*)d_out;                 // (64,4096,64)

    cudaFuncSetAttribute(lstm_hmma_kernel,
                         cudaFuncAttributeMaxDynamicSharedMemorySize, SMEM_TOTAL);

    const int n_blocks = (64 * 4096) / SEQ_CTA;  // 1024
    lstm_hmma_kernel<<<n_blocks, THREADS, SMEM_TOTAL>>>(x, W_ih, W_hh, b_ih, b_hh, out);
}

// round 13
// speedup vs baseline: 3.7537x; 1.5804x over previous
#include <cuda_runtime.h>
#include <cuda_fp16.h>
#include <cstdint>

// LSTM via legacy mma.sync (plain sm_100 target — tcgen05 unavailable).
// H=64, gates=256, T=50, 262144 seqs, input dim 1.
// CTA = 256 seqs, 16 warps; warp owns 16 seqs (one m16 tile) x 256 gates.
// D[16x256] = h[16x64] @ W_hh^T (fp16 x fp16, fp32 accum)  PLUS an extra
// k8 MMA tile folding x*w_in + bias into D:
//   A-extra row s = [x_hi, x_lo, 1, 1, 0..]  (x 2-limb fp16, exact)
//   B-extra row g = [w_hi, w_hi, b_hi, b_lo, 0..]  (bias 2-limb, exact)
// so gates come straight out of the accumulator (R12 finding: kernel is
// issue-bound, epilogue instructions ~80% of the stream; this removes the
// per-cell gate FMAs, D-merge adds, and per-jt bias LDS).
// Single accumulator per gate-block (chain depth 5 — depth proven non-
// binding in R12). Epilogue: sigmoid/tanh via ex2/rcp, h packed with
// cvt.rn.f16x2.f32, stored fp16 to warp-private A-tile rows.
// No block syncs in the main loop — only __syncwarp (state warp-private).

typedef uint32_t u32;

#define THREADS 512
#define TSTEPS  50
#define SEQ_CTA 256

// smem byte offsets
#define OFF_WHI 0        // W_hh fp16 [256 g][64 k], 128B rows, XOR-swz  (32KB)
#define OFF_HHI 32768    // h [256 s][64 k] f16, 128B rows, swz          (32KB)
#define OFF_XT  65536    // A-extra [256 s][8 halves] = 16B rows          (4KB)
#define OFF_WX  69632    // B-extra [256 g][8 halves] = 16B rows          (4KB)
#define OFF_XS  73728    // x staged [50][256] f32                       (50KB)
#define SMEM_TOTAL 124928

__device__ __forceinline__ u32 smem_u32(const void* p) {
    u32 a;
    asm("{ .reg .u64 t; cvta.to.shared.u64 t, %1; cvt.u32.u64 %0, t; }"
        : "=r"(a) : "l"(p));
    return a;
}

#define LDSM4(r, a) asm volatile( \
    "ldmatrix.sync.aligned.m8n8.x4.shared.b16 {%0,%1,%2,%3}, [%4];" \
    : "=r"((r)[0]), "=r"((r)[1]), "=r"((r)[2]), "=r"((r)[3]) : "r"(a))

#define LDSM2(r, a) asm volatile( \
    "ldmatrix.sync.aligned.m8n8.x2.shared.b16 {%0,%1}, [%2];" \
    : "=r"((r)[0]), "=r"((r)[1]) : "r"(a))

#define LDSM1(r, a) asm volatile( \
    "ldmatrix.sync.aligned.m8n8.x1.shared.b16 {%0}, [%1];" \
    : "=r"(r) : "r"(a))

#define MMA(d, a, b0, b1) asm volatile( \
    "mma.sync.aligned.m16n8k16.row.col.f32.f16.f16.f32 " \
    "{%0,%1,%2,%3}, {%4,%5,%6,%7}, {%8,%9}, {%0,%1,%2,%3};" \
    : "+f"((d)[0]), "+f"((d)[1]), "+f"((d)[2]), "+f"((d)[3]) \
    : "r"((a)[0]), "r"((a)[1]), "r"((a)[2]), "r"((a)[3]), "r"(b0), "r"(b1))

#define MMAK8(d, a, b0) asm volatile( \
    "mma.sync.aligned.m16n8k8.row.col.f32.f16.f16.f32 " \
    "{%0,%1,%2,%3}, {%4,%5}, {%6}, {%0,%1,%2,%3};" \
    : "+f"((d)[0]), "+f"((d)[1]), "+f"((d)[2]), "+f"((d)[3]) \
    : "r"((a)[0]), "r"((a)[1]), "r"(b0))

__device__ __forceinline__ float ex2f_(float x){float r;asm("ex2.approx.f32 %0,%1;":"=f"(r):"f"(x));return r;}
__device__ __forceinline__ float rcpf_(float x){float r;asm("rcp.approx.f32 %0,%1;":"=f"(r):"f"(x));return r;}

__device__ __forceinline__ u32 h2u(__half a, __half b) {
    __half2 v = __halves2half2(a, b);
    return *(u32*)&v;
}

extern "C" __global__ void __launch_bounds__(THREADS, 1)
lstm_hmma_kernel(const float* __restrict__ x_g,
                 const float* __restrict__ W_ih,
                 const float* __restrict__ W_hh,
                 const float* __restrict__ b_ih,
                 const float* __restrict__ b_hh,
                 float* __restrict__ out)
{
    extern __shared__ char sm[];
    const u32 S = smem_u32(sm);
    const int tid  = threadIdx.x;
    const int lane = tid & 31;
    const int w    = tid >> 5;           // 0..15
    const int seq0 = blockIdx.x * SEQ_CTA;

    // ---------------- one-time staging ----------------
    // W_hh fp16; byte(g, k) = g*128 + ((k*2) ^ ((g&7)<<4))
    for (int i = tid; i < 256 * 64; i += THREADS) {
        int g = i >> 6, k = i & 63;
        u32 off = (u32)(g * 128) + (u32)((k * 2) ^ ((g & 7) << 4));
        *(__half*)(sm + OFF_WHI + off) = __float2half_rn(W_hh[i]);
    }
    // h tile zero (h0 = 0)
    for (int i = tid; i < 32768 / 4; i += THREADS)
        ((u32*)(sm + OFF_HHI))[i] = 0u;
    // x staged: xs[t][s]
    float* xs = (float*)(sm + OFF_XS);
    for (int i = tid; i < SEQ_CTA * TSTEPS; i += THREADS) {
        int s = i / TSTEPS, t = i - s * TSTEPS;
        xs[t * SEQ_CTA + s] = x_g[(size_t)(seq0 + s) * TSTEPS + t];
    }
    // B-extra: row g = [w_hi, w_hi, b_hi, b_lo, 0,0,0,0]
    const __half ONE = __float2half_rn(1.0f);
    for (int g = tid; g < 256; g += THREADS) {
        __half wh = __float2half_rn(W_ih[g]);
        float  b  = b_ih[g] + b_hh[g];
        __half bh = __float2half_rn(b);
        __half bl = __float2half_rn(b - __half2float(bh));
        *(uint4*)(sm + OFF_WX + g * 16) =
            make_uint4(h2u(wh, wh), h2u(bh, bl), 0u, 0u);
    }
    // A-extra (t=0): row s = [x_hi, x_lo, 1, 1, 0,0,0,0]
    for (int s = tid; s < SEQ_CTA; s += THREADS) {
        float x = xs[0 * SEQ_CTA + s];  // staged above by same thread? no —
        // xs may not be fully written by this thread's strides; use gmem:
        x = x_g[(size_t)(seq0 + s) * TSTEPS + 0];
        __half xh = __float2half_rn(x);
        __half xl = __float2half_rn(x - __half2float(xh));
        *(uint4*)(sm + OFF_XT + s * 16) =
            make_uint4(h2u(xh, xl), h2u(ONE, ONE), 0u, 0u);
    }
    __syncthreads();

    // ---------------- per-thread constants ----------------
    const int r16   = lane & 15;          // A-frag row within m16
    const int khalf = lane >> 4;          // A-frag k-half (0/1)
    const int swzA  = (lane & 7) << 4;
    const u32 a_row = S + OFF_HHI + (u32)((w * 16 + r16) * 128);
    u32 acol[4];
    #pragma unroll
    for (int kt = 0; kt < 4; kt++)
        acol[kt] = (u32)((kt * 32 + khalf * 16) ^ swzA);
    // A-extra ldmatrix.x2 address (lanes 0..15 meaningful)
    const u32 axt = S + OFF_XT + (u32)((w * 16 + r16) * 16);
    // main B addresses
    const int brow7 = lane & 7;
    const u32 swzB  = (u32)(brow7 << 4);
    const u32 bcol0 = (u32)(((lane >> 3) * 16)      ^ swzB);  // k 0..31
    const u32 bcol1 = (u32)((64 + (lane >> 3) * 16) ^ swzB);  // k 32..63
    const u32 brow_off = (u32)(brow7 * 128);
    // B-extra ldmatrix.x1 base (lanes 0..7 meaningful): row = gate
    const u32 wx_row = S + OFF_WX + (u32)(brow7 * 16);
    // epilogue cell ownership
    const int qr = lane >> 2;             // row-in-8
    const int qc = (lane & 3) * 2;        // j offset within n8
    const u32 swzH = (u32)(qr << 4);
    // A-extra per-step store (lane < 16 stores its row's x limbs)
    const u32 xt_st = S + OFF_XT + (u32)((w * 16 + (lane & 15)) * 16);

    const float L2E  = 1.4426950408889634f;
    const float L2E2 = 2.885390081777927f;

    float c[2][8][2];
    #pragma unroll
    for (int b = 0; b < 2; b++)
        #pragma unroll
        for (int j = 0; j < 8; j++) { c[b][j][0] = 0.f; c[b][j][1] = 0.f; }

    // ---------------- time loop ----------------
    #pragma unroll 1
    for (int t = 0; t < TSTEPS; t++) {
        const bool last = (t == TSTEPS - 1);
        __syncwarp();   // prev step's h stores + XT stores visible to ldmatrix

        // A fragments: h (4x LDSM4) + extra (1x LDSM2)
        u32 AH[4][4], AX[2];
        #pragma unroll
        for (int kt = 0; kt < 4; kt++)
            LDSM4(AH[kt], a_row + acol[kt]);
        LDSM2(AX, axt);

        #pragma unroll
        for (int jt = 0; jt < 8; jt++) {
            float D[4][4];
            #pragma unroll
            for (int gb = 0; gb < 4; gb++) {
                D[gb][0] = 0.f; D[gb][1] = 0.f; D[gb][2] = 0.f; D[gb][3] = 0.f;
            }

            #pragma unroll
            for (int gb = 0; gb < 4; gb++) {
                const u32 bb = S + OFF_WHI
                             + (u32)((gb * 64 + jt * 8) * 128) + brow_off;
                u32 bh[8], bx;
                LDSM4(bh + 0, bb + bcol0);
                LDSM4(bh + 4, bb + bcol1);
                LDSM1(bx, wx_row + (u32)((gb * 64 + jt * 8) * 16));
                MMAK8(D[gb], AX, bx);              // x*w_in + bias
                MMA(D[gb], AH[0], bh[0], bh[1]);
                MMA(D[gb], AH[1], bh[2], bh[3]);
                MMA(D[gb], AH[2], bh[4], bh[5]);
                MMA(D[gb], AH[3], bh[6], bh[7]);
            }

            // epilogue: 4 cells (2 rows x 2 cols); gates come straight from D
            #pragma unroll
            for (int rr = 0; rr < 2; rr++) {
                float hvv[2];
                #pragma unroll
                for (int cc = 0; cc < 2; cc++) {
                    const int di = rr * 2 + cc;
                    float Gi = D[0][di];
                    float Gf = D[1][di];
                    float Gg = D[2][di];
                    float Go = D[3][di];
                    float ef = ex2f_(Gf * -L2E);
                    float sf = rcpf_(1.0f + ef);
                    float ei = ex2f_(Gi * -L2E);
                    float eg = ex2f_(Gg * -L2E2);
                    float itn = (1.0f - eg) * rcpf_((1.0f + ei) * (1.0f + eg));
                    float cn = fmaf(sf, c[rr][jt][cc], itn);
                    c[rr][jt][cc] = cn;
                    float eo = ex2f_(Go * -L2E);
                    float ec = ex2f_(fminf(cn * -L2E2, 80.0f));
                    hvv[cc] = (1.0f - ec) * rcpf_((1.0f + eo) * (1.0f + ec));
                }
                const int row = w * 16 + rr * 8 + qr;
                if (!last) {
                    u32 hpk;
                    asm("cvt.rn.f16x2.f32 %0, %1, %2;"
                        : "=r"(hpk) : "f"(hvv[1]), "f"(hvv[0]));
                    u32 off = (u32)(row * 128)
                            + (u32)(((jt * 8 + qc) * 2) ^ swzH);
                    *(u32*)(sm + OFF_HHI + off) = hpk;
                } else {
                    *(float2*)(out + (size_t)(seq0 + row) * 64 + jt * 8 + qc) =
                        make_float2(hvv[0], hvv[1]);
                }
            }
        }

        // stage next step's x limbs into A-extra (cols 0-1 only; ones static)
        if (!last && lane < 16) {
            float x = xs[(t + 1) * SEQ_CTA + w * 16 + lane];
            __half xh = __float2half_rn(x);
            __half xl = __float2half_rn(x - __half2float(xh));
            *(u32*)(sm + (xt_st - S)) = h2u(xh, xl);
        }
    }
}

extern "C" void kernel_launch(void* const* d_in, const int* in_sizes, int n_in,
                              void* d_out, int out_size) {
    const float* x    = (const float*)d_in[0];  // dynamic (64,4096,50)
    const float* W_ih = (const float*)d_in[1];  // (256,1)
    const float* W_hh = (const float*)d_in[2];  // (256,64)
    const float* b_ih = (const float*)d_in[3];  // (256,)
    const float* b_hh = (const float*)d_in[4];  // (256,)
    float* out = (float*)d_out;                 // (64,4096,64)

    cudaFuncSetAttribute(lstm_hmma_kernel,
                         cudaFuncAttributeMaxDynamicSharedMemorySize, SMEM_TOTAL);

    const int n_blocks = (64 * 4096) / SEQ_CTA;  // 1024
    lstm_hmma_kernel<<<n_blocks, THREADS, SMEM_TOTAL>>>(x, W_ih, W_hh, b_ih, b_hh, out);
}

// round 15
// speedup vs baseline: 3.8034x; 1.0133x over previous
#include <cuda_runtime.h>
#include <cuda_fp16.h>
#include <cstdint>

// LSTM via legacy mma.sync (plain sm_100 target — tcgen05 unavailable).
// H=64, gates=256, T=50, 262144 seqs, input dim 1.
// CTA = 256 seqs, 16 warps; warp owns 16 seqs (one m16 tile) x 256 gates.
// D[16x256] = h[16x64] @ W_hh^T (fp16 x fp16, fp32 accum) + extra k8 MMA
// folding x*w_in + bias (x 2-limb, bias 2-limb: exact; w_in fp16).
// R14: FlashAttention-style register reuse — the f32 D fragment layout of
// m16n8k16 equals the A f16x2 operand layout when n(step t) -> k(step t+1),
// so post-nonlinearity h is packed (cvt.rn.f16x2.f32) STRAIGHT into next
// step's A registers. h never touches smem: no STS, no A-ldmatrix, no
// __syncwarp in the main loop (smem is read-only W / B-extra / x there).
// The x-limb A fragment is built by lane select, not ldmatrix.
// Epilogue: sigmoid/tanh via ex2/rcp (arithmetic identical to R13).

typedef uint32_t u32;

#define THREADS 512
#define TSTEPS  50
#define SEQ_CTA 256

// smem byte offsets
#define OFF_WHI 0        // W_hh fp16 [256 g][64 k], 128B rows, XOR-swz  (32KB)
#define OFF_WX  32768    // B-extra [256 g][8 halves] = 16B rows          (4KB)
#define OFF_XS  36864    // x staged [50][256] f32                       (50KB)
#define SMEM_TOTAL 88064

__device__ __forceinline__ u32 smem_u32(const void* p) {
    u32 a;
    asm("{ .reg .u64 t; cvta.to.shared.u64 t, %1; cvt.u32.u64 %0, t; }"
        : "=r"(a) : "l"(p));
    return a;
}

#define LDSM4(r, a) asm volatile( \
    "ldmatrix.sync.aligned.m8n8.x4.shared.b16 {%0,%1,%2,%3}, [%4];" \
    : "=r"((r)[0]), "=r"((r)[1]), "=r"((r)[2]), "=r"((r)[3]) : "r"(a))

#define LDSM1(r, a) asm volatile( \
    "ldmatrix.sync.aligned.m8n8.x1.shared.b16 {%0}, [%1];" \
    : "=r"(r) : "r"(a))

#define MMA(d, a, b0, b1) asm volatile( \
    "mma.sync.aligned.m16n8k16.row.col.f32.f16.f16.f32 " \
    "{%0,%1,%2,%3}, {%4,%5,%6,%7}, {%8,%9}, {%0,%1,%2,%3};" \
    : "+f"((d)[0]), "+f"((d)[1]), "+f"((d)[2]), "+f"((d)[3]) \
    : "r"((a)[0]), "r"((a)[1]), "r"((a)[2]), "r"((a)[3]), "r"(b0), "r"(b1))

#define MMAK8(d, a, b0) asm volatile( \
    "mma.sync.aligned.m16n8k8.row.col.f32.f16.f16.f32 " \
    "{%0,%1,%2,%3}, {%4,%5}, {%6}, {%0,%1,%2,%3};" \
    : "+f"((d)[0]), "+f"((d)[1]), "+f"((d)[2]), "+f"((d)[3]) \
    : "r"((a)[0]), "r"((a)[1]), "r"(b0))

__device__ __forceinline__ float ex2f_(float x){float r;asm("ex2.approx.f32 %0,%1;":"=f"(r):"f"(x));return r;}
__device__ __forceinline__ float rcpf_(float x){float r;asm("rcp.approx.f32 %0,%1;":"=f"(r):"f"(x));return r;}

__device__ __forceinline__ u32 h2u(__half a, __half b) {
    __half2 v = __halves2half2(a, b);
    return *(u32*)&v;
}
// pack two f32 -> f16x2 with lo = first arg
__device__ __forceinline__ u32 pk16(float lo, float hi) {
    u32 r;
    asm("cvt.rn.f16x2.f32 %0, %1, %2;" : "=r"(r) : "f"(hi), "f"(lo));
    return r;
}

extern "C" __global__ void __launch_bounds__(THREADS, 1)
lstm_hmma_kernel(const float* __restrict__ x_g,
                 const float* __restrict__ W_ih,
                 const float* __restrict__ W_hh,
                 const float* __restrict__ b_ih,
                 const float* __restrict__ b_hh,
                 float* __restrict__ out)
{
    extern __shared__ char sm[];
    const u32 S = smem_u32(sm);
    const int tid  = threadIdx.x;
    const int lane = tid & 31;
    const int w    = tid >> 5;           // 0..15
    const int seq0 = blockIdx.x * SEQ_CTA;

    // ---------------- one-time staging ----------------
    // W_hh fp16; byte(g, k) = g*128 + ((k*2) ^ ((g&7)<<4))
    for (int i = tid; i < 256 * 64; i += THREADS) {
        int g = i >> 6, k = i & 63;
        u32 off = (u32)(g * 128) + (u32)((k * 2) ^ ((g & 7) << 4));
        *(__half*)(sm + OFF_WHI + off) = __float2half_rn(W_hh[i]);
    }
    // x staged: xs[t][s]
    float* xs = (float*)(sm + OFF_XS);
    for (int i = tid; i < SEQ_CTA * TSTEPS; i += THREADS) {
        int s = i / TSTEPS, t = i - s * TSTEPS;
        xs[t * SEQ_CTA + s] = x_g[(size_t)(seq0 + s) * TSTEPS + t];
    }
    // B-extra: row g = [w_hi, w_hi, b_hi, b_lo, 0,0,0,0]
    for (int g = tid; g < 256; g += THREADS) {
        __half wh = __float2half_rn(W_ih[g]);
        float  b  = b_ih[g] + b_hh[g];
        __half bh = __float2half_rn(b);
        __half bl = __float2half_rn(b - __half2float(bh));
        *(uint4*)(sm + OFF_WX + g * 16) =
            make_uint4(h2u(wh, wh), h2u(bh, bl), 0u, 0u);
    }
    __syncthreads();

    // ---------------- per-thread constants ----------------
    const int tig   = lane & 3;           // thread-in-group (col pair)
    const int qr    = lane >> 2;          // row-in-8 (groupID)
    const int qc    = tig * 2;            // col offset within n8
    const int brow7 = lane & 7;
    const u32 swzB  = (u32)(brow7 << 4);
    const u32 bcol0 = (u32)(((lane >> 3) * 16)      ^ swzB);  // k 0..31
    const u32 bcol1 = (u32)((64 + (lane >> 3) * 16) ^ swzB);  // k 32..63
    const u32 brow_off = (u32)(brow7 * 128);
    const u32 wx_row = S + OFF_WX + (u32)(brow7 * 16);
    const u32 ONE2 = 0x3C003C00u;         // (1.0h, 1.0h)

    const float L2E  = 1.4426950408889634f;
    const float L2E2 = 2.885390081777927f;

    float c[2][8][2];                     // [row-half][jt][col]
    #pragma unroll
    for (int b = 0; b < 2; b++)
        #pragma unroll
        for (int j = 0; j < 8; j++) { c[b][j][0] = 0.f; c[b][j][1] = 0.f; }

    // A fragments (h in f16x2, register-carried). h0 = 0.
    // AH[kt] = { P01[2kt], P23[2kt], P01[2kt+1], P23[2kt+1] } where
    // P01[jt] = pack(h[qr][8jt+qc], h[qr][8jt+qc+1]), P23 = rows qr+8.
    u32 AH[4][4];
    #pragma unroll
    for (int kt = 0; kt < 4; kt++)
        #pragma unroll
        for (int i = 0; i < 4; i++) AH[kt][i] = 0u;

    // ---------------- time loop ----------------
    #pragma unroll 1
    for (int t = 0; t < TSTEPS; t++) {
        const bool last = (t == TSTEPS - 1);

        // AX (extra k8 A fragment) built by lane select:
        // row pattern = [x_hi, x_lo, 1, 1, 0,0,0,0]
        u32 AX[2];
        {
            float xa = xs[t * SEQ_CTA + w * 16 + qr];
            float xb = xs[t * SEQ_CTA + w * 16 + 8 + qr];
            __half xah = __float2half_rn(xa);
            __half xbh = __float2half_rn(xb);
            u32 pa = h2u(xah, __float2half_rn(xa - __half2float(xah)));
            u32 pb = h2u(xbh, __float2half_rn(xb - __half2float(xbh)));
            AX[0] = (tig == 0) ? pa : ((tig == 1) ? ONE2 : 0u);
            AX[1] = (tig == 0) ? pb : ((tig == 1) ? ONE2 : 0u);
        }

        u32 AHn[4][4];

        #pragma unroll
        for (int jt = 0; jt < 8; jt++) {
            float D[4][4];
            #pragma unroll
            for (int gb = 0; gb < 4; gb++) {
                D[gb][0] = 0.f; D[gb][1] = 0.f; D[gb][2] = 0.f; D[gb][3] = 0.f;
            }

            #pragma unroll
            for (int gb = 0; gb < 4; gb++) {
                const u32 bb = S + OFF_WHI
                             + (u32)((gb * 64 + jt * 8) * 128) + brow_off;
                u32 bh[8], bx;
                LDSM4(bh + 0, bb + bcol0);
                LDSM4(bh + 4, bb + bcol1);
                LDSM1(bx, wx_row + (u32)((gb * 64 + jt * 8) * 16));
                MMAK8(D[gb], AX, bx);              // x*w_in + bias
                MMA(D[gb], AH[0], bh[0], bh[1]);
                MMA(D[gb], AH[1], bh[2], bh[3]);
                MMA(D[gb], AH[2], bh[4], bh[5]);
                MMA(D[gb], AH[3], bh[6], bh[7]);
            }

            // epilogue: 4 cells (rr=0: row qr; rr=1: row qr+8)
            #pragma unroll
            for (int rr = 0; rr < 2; rr++) {
                float hvv[2];
                #pragma unroll
                for (int cc = 0; cc < 2; cc++) {
                    const int di = rr * 2 + cc;
                    float Gi = D[0][di];
                    float Gf = D[1][di];
                    float Gg = D[2][di];
                    float Go = D[3][di];
                    float ef = ex2f_(Gf * -L2E);
                    float sf = rcpf_(1.0f + ef);
                    float ei = ex2f_(Gi * -L2E);
                    float eg = ex2f_(Gg * -L2E2);
                    float itn = (1.0f - eg) * rcpf_((1.0f + ei) * (1.0f + eg));
                    float cn = fmaf(sf, c[rr][jt][cc], itn);
                    c[rr][jt][cc] = cn;
                    float eo = ex2f_(Go * -L2E);
                    float ec = ex2f_(fminf(cn * -L2E2, 80.0f));
                    hvv[cc] = (1.0f - ec) * rcpf_((1.0f + eo) * (1.0f + ec));
                }
                if (!last) {
                    // next step's A register, no smem round-trip
                    AHn[jt >> 1][(jt & 1) * 2 + rr] = pk16(hvv[0], hvv[1]);
                } else {
                    const int row = w * 16 + rr * 8 + qr;
                    *(float2*)(out + (size_t)(seq0 + row) * 64 + jt * 8 + qc) =
                        make_float2(hvv[0], hvv[1]);
                }
            }
        }

        if (!last) {
            #pragma unroll
            for (int kt = 0; kt < 4; kt++)
                #pragma unroll
                for (int i = 0; i < 4; i++) AH[kt][i] = AHn[kt][i];
        }
    }
}

extern "C" void kernel_launch(void* const* d_in, const int* in_sizes, int n_in,
                              void* d_out, int out_size) {
    const float* x    = (const float*)d_in[0];  // dynamic (64,4096,50)
    const float* W_ih = (const float*)d_in[1];  // (256,1)
    const float* W_hh = (const float*)d_in[2];  // (256,64)
    const float* b_ih = (const float*)d_in[3];  // (256,)
    const float* b_hh = (const float*)d_in[4];  // (256,)
    float* out = (float*)d_out;                 // (64,4096,64)

    cudaFuncSetAttribute(lstm_hmma_kernel,
                         cudaFuncAttributeMaxDynamicSharedMemorySize, SMEM_TOTAL);

    const int n_blocks = (64 * 4096) / SEQ_CTA;  // 1024
    lstm_hmma_kernel<<<n_blocks, THREADS, SMEM_TOTAL>>>(x, W_ih, W_hh, b_ih, b_hh, out);
}